// round 13
// baseline (speedup 1.0000x reference)
#include <cuda_runtime.h>
#include <cstdint>

// ---------------------------------------------------------------------------
// TemporalAttentionPooling (GB300 / sm_103a) — Round 12
//   scores = tanh(x @ W1 + b1) @ W2 + b2   (MLP 128->32->1)
//   per-segment softmax (max-free: bounded scores) -> pooled = sum e x / sum e
//
// R12 vs R11 (234.2 us; L1 76%, fma 50% — crossbar-bound):
//   - RPG 16->24, NWARP 12->8: W1 smem reads amortized over 24 rows
//     (8 -> 5.3 LDS/row; total ~18 -> ~15.3, -15% L1 traffic)
//   - smem 219 KB: 16 KB shared W1 + 8 warps x 2 bufs x 24 rows x 528 B
//   everything else identical to R11 (flat streaming, cp.async double
//   buffer, stride-132 bank skew, fast/slow pid paths, atomic flush,
//   fused normalize behind grid-wide spin barrier)
// ---------------------------------------------------------------------------

#define RPG     24
#define PMAX    16384
#define NWARP   8
#define NTHR    (NWARP * 32)
#define GRID    152
#define RSTRIDE 132                  // floats per staged row (528 B)
#define BUFF    (RPG * RSTRIDE)      // 3168 floats per buffer
#define WSTRIDE (2 * BUFF)           // 6336 floats per warp (2 buffers)

__device__ float g_acc[PMAX * 128];  // unnormalized pooled sums (self-zeroing)
__device__ float g_S[PMAX];          // exp-sum denominators    (self-zeroing)
__device__ int   g_arrive;           // grid barrier (self-resetting)
__device__ int   g_depart;

static __device__ __forceinline__ unsigned long long f2pack(float lo, float hi) {
    unsigned long long r;
    asm("mov.b64 %0, {%1, %2};" : "=l"(r) : "f"(lo), "f"(hi));
    return r;
}
static __device__ __forceinline__ void f2unpack(unsigned long long v, float& lo, float& hi) {
    asm("mov.b64 {%0, %1}, %2;" : "=f"(lo), "=f"(hi) : "l"(v));
}
static __device__ __forceinline__ unsigned long long ffma2(unsigned long long a,
                                                           unsigned long long b,
                                                           unsigned long long c) {
    unsigned long long d;
    asm("fma.rn.f32x2 %0, %1, %2, %3;" : "=l"(d) : "l"(a), "l"(b), "l"(c));
    return d;
}
static __device__ __forceinline__ void cp_async16(uint32_t dst, const void* src, int pred) {
    asm volatile(
        "{ .reg .pred p;\n"
        "  setp.ne.u32 p, %2, 0;\n"
        "  @p cp.async.cg.shared.global [%0], [%1], 16; }\n"
        :: "r"(dst), "l"(src), "r"(pred));
}
#define CP_COMMIT() asm volatile("cp.async.commit_group;" ::: "memory")
#define CP_WAIT1()  asm volatile("cp.async.wait_group 1;" ::: "memory")

// cheap accurate tanh: (e^{2h}-1)/(e^{2h}+1); |h| bounded so no overflow
static __device__ __forceinline__ float tanh_fast(float h) {
    float t = __expf(2.0f * h);
    return __fdividef(t - 1.0f, t + 1.0f);
}

static __device__ __forceinline__ void flush_seg(int pidv,
                                                 unsigned long long& pa0,
                                                 unsigned long long& pa1,
                                                 float& Ssum, int lane) {
    if (pidv >= 0) {
        float a, b, c, d;
        f2unpack(pa0, a, b);
        f2unpack(pa1, c, d);
        float* dst = g_acc + (size_t)pidv * 128 + 4 * lane;
        atomicAdd(dst + 0, a);
        atomicAdd(dst + 1, b);
        atomicAdd(dst + 2, c);
        atomicAdd(dst + 3, d);
        if (lane == 0) atomicAdd(&g_S[pidv], Ssum);
    }
    pa0 = 0ull; pa1 = 0ull; Ssum = 0.0f;
}

// dynamic smem: [0,16K) w1t; [16K, 16K + NWARP*WSTRIDE*4) per-warp stages
#define SMEM_BYTES (16384 + NWARP * WSTRIDE * 4)

__global__ void __launch_bounds__(NTHR, 1)
k_main(const float* __restrict__ x,
       const int*   __restrict__ pid,
       const float* __restrict__ W1,   // (128, 32) row-major
       const float* __restrict__ b1,   // (32,)
       const float* __restrict__ W2,   // (32,)
       const float* __restrict__ b2,   // (1,)
       float* __restrict__ out,        // (P,128) then pids (P,) if present
       int n, int nUnits, int P, int has_pids) {
    extern __shared__ __align__(16) char smem_raw[];
    ulonglong2* w1t   = reinterpret_cast<ulonglong2*>(smem_raw);
    float*      stage = reinterpret_cast<float*>(smem_raw + 16384);

    const int tid  = threadIdx.x;
    const int wid  = tid >> 5;
    const int lane = tid & 31;
    const int j2   = lane & 7;      // hidden group: j = 4*j2..4*j2+3
    const int r2   = lane >> 3;     // row subgroup base: rows r2+4*rr

    // ---- k-paired W1 table (packing verified R4..R11) ----------------------
    {
        float* w1f = reinterpret_cast<float*>(w1t);
        for (int q4 = tid; q4 < 4096; q4 += NTHR) {
            int q    = q4 >> 2, slot = q4 & 3;
            int kp   = q >> 4, rem = q & 15;
            int part = rem >> 3, jq = rem & 7;
            int j    = 4 * jq + 2 * part + (slot >> 1);
            int krow = 2 * kp + (slot & 1);
            w1f[q4] = W1[krow * 32 + j];
        }
    }
    const float4 b1q = reinterpret_cast<const float4*>(b1)[j2];
    const float4 w2q = reinterpret_cast<const float4*>(W2)[j2];
    const float  b2s = b2[0];
    __syncthreads();

    const uint32_t st_sh =
        (uint32_t)__cvta_generic_to_shared(stage) + (uint32_t)(wid * WSTRIDE * 4);
    float* const stw = stage + wid * WSTRIDE;

    // ---- contiguous unit range for this warp -------------------------------
    const int nW = GRID * NWARP;
    const int gw = blockIdx.x * NWARP + wid;
    const long long u0 = ((long long)gw * nUnits) / nW;
    const long long u1 = ((long long)(gw + 1) * nUnits) / nW;

    unsigned long long pa0 = 0ull, pa1 = 0ull;  // running pooled dims 4l..4l+3
    float Ssum   = 0.0f;
    int   curPid = -1;

    int ibuf = 0;
    int pidNext = -2;
    if (u0 < u1) {                    // prologue: issue unit u0 into buf 0
        const int   br  = (int)(u0 * RPG);
        const float* sp = x + (size_t)br * 128 + lane * 4;
        if (br + RPG <= n) {
#pragma unroll
            for (int r = 0; r < RPG; r++)
                cp_async16(st_sh + (uint32_t)(r * 528 + (lane << 4)),
                           sp + (size_t)r * 128, 1);
        } else {
#pragma unroll
            for (int r = 0; r < RPG; r++)
                cp_async16(st_sh + (uint32_t)(r * 528 + (lane << 4)),
                           sp + (size_t)r * 128, (br + r) < n);
        }
        if (lane < RPG && (br + lane) < n) pidNext = pid[br + lane];
    }
    CP_COMMIT();

    for (long long uu = u0; uu < u1; ++uu) {
        const int pidCur = pidNext;
        const int nb = ibuf ^ 1;
        if (uu + 1 < u1) {            // issue next unit (linear addresses)
            const int   br  = (int)((uu + 1) * RPG);
            const float* sp = x + (size_t)br * 128 + lane * 4;
            const uint32_t xbA = st_sh + (uint32_t)(nb * BUFF * 4);
            if (br + RPG <= n) {
#pragma unroll
                for (int r = 0; r < RPG; r++)
                    cp_async16(xbA + (uint32_t)(r * 528 + (lane << 4)),
                               sp + (size_t)r * 128, 1);
            } else {
#pragma unroll
                for (int r = 0; r < RPG; r++)
                    cp_async16(xbA + (uint32_t)(r * 528 + (lane << 4)),
                               sp + (size_t)r * 128, (br + r) < n);
            }
            pidNext = -2;
            if (lane < RPG && (br + lane) < n) pidNext = pid[br + lane];
        }
        CP_COMMIT();
        CP_WAIT1();                   // current unit complete

        const int baseRow   = (int)(uu * RPG);
        const int rowsValid = min(RPG, n - baseRow);
        const float* xb = stw + ibuf * BUFF;

        // ---- MLP: 24 rows, acc[6 row-subgroups][4 hidden] ------------------
        unsigned long long acc[6][4];
#pragma unroll
        for (int rr = 0; rr < 6; rr++)
#pragma unroll
            for (int jj = 0; jj < 4; jj++) acc[rr][jj] = 0ull;

#pragma unroll 4
        for (int t = 0; t < 32; t++) {
            ulonglong2 wA0 = w1t[32 * t + j2];
            ulonglong2 wA1 = w1t[32 * t + 8 + j2];
            ulonglong2 wB0 = w1t[32 * t + 16 + j2];
            ulonglong2 wB1 = w1t[32 * t + 24 + j2];
#pragma unroll
            for (int rr = 0; rr < 6; rr++) {
                const int row = r2 + 4 * rr;
                ulonglong2 xq = *reinterpret_cast<const ulonglong2*>(
                                    xb + row * RSTRIDE + t * 4);
                acc[rr][0] = ffma2(xq.x, wA0.x, acc[rr][0]);
                acc[rr][1] = ffma2(xq.x, wA0.y, acc[rr][1]);
                acc[rr][2] = ffma2(xq.x, wA1.x, acc[rr][2]);
                acc[rr][3] = ffma2(xq.x, wA1.y, acc[rr][3]);
                acc[rr][0] = ffma2(xq.y, wB0.x, acc[rr][0]);
                acc[rr][1] = ffma2(xq.y, wB0.y, acc[rr][1]);
                acc[rr][2] = ffma2(xq.y, wB1.x, acc[rr][2]);
                acc[rr][3] = ffma2(xq.y, wB1.y, acc[rr][3]);
            }
        }

        // ---- epilogue: tanh + W2 dot + j2-octet reduce -> e per row --------
        float ev[6];
#pragma unroll
        for (int rr = 0; rr < 6; rr++) {
            float s = 0.0f;
#pragma unroll
            for (int jj = 0; jj < 4; jj++) {
                float lo, hi;
                f2unpack(acc[rr][jj], lo, hi);
                float h = lo + hi + reinterpret_cast<const float*>(&b1q)[jj];
                s += tanh_fast(h) * reinterpret_cast<const float*>(&w2q)[jj];
            }
            s += __shfl_xor_sync(0xffffffffu, s, 1);
            s += __shfl_xor_sync(0xffffffffu, s, 2);
            s += __shfl_xor_sync(0xffffffffu, s, 4);
            ev[rr] = __expf(s + b2s);   // bounded scores: no overflow
        }

        // ---- pooling -------------------------------------------------------
        const int pidFirst = __shfl_sync(0xffffffffu, pidCur, 0);
        const int pidLast  = __shfl_sync(0xffffffffu, pidCur, RPG - 1);
        if (pidFirst == pidLast && rowsValid == RPG) {
            // fast path: whole unit in one segment (sorted pids)
            if (pidFirst != curPid) {
                flush_seg(curPid, pa0, pa1, Ssum, lane);
                curPid = pidFirst;
            }
            float s6 = ((ev[0] + ev[1]) + (ev[2] + ev[3])) + (ev[4] + ev[5]);
            s6 += __shfl_xor_sync(0xffffffffu, s6, 8);
            s6 += __shfl_xor_sync(0xffffffffu, s6, 16);
            Ssum += s6;
#pragma unroll
            for (int r = 0; r < RPG; r++) {
                float ew = __shfl_sync(0xffffffffu, ev[r >> 2], (r & 3) * 8);
                ulonglong2 xq = *reinterpret_cast<const ulonglong2*>(
                                    xb + r * RSTRIDE + lane * 4);
                unsigned long long eq = f2pack(ew, ew);
                pa0 = ffma2(xq.x, eq, pa0);
                pa1 = ffma2(xq.y, eq, pa1);
            }
        } else {
            // slow path: per-row pid tracking
#pragma unroll
            for (int r = 0; r < RPG; r++) {
                if (r < rowsValid) {
                    int pr = __shfl_sync(0xffffffffu, pidCur, r);
                    if (pr != curPid) {
                        flush_seg(curPid, pa0, pa1, Ssum, lane);
                        curPid = pr;
                    }
                    float ew = __shfl_sync(0xffffffffu, ev[r >> 2], (r & 3) * 8);
                    Ssum += ew;
                    ulonglong2 xq = *reinterpret_cast<const ulonglong2*>(
                                        xb + r * RSTRIDE + lane * 4);
                    unsigned long long eq = f2pack(ew, ew);
                    pa0 = ffma2(xq.x, eq, pa0);
                    pa1 = ffma2(xq.y, eq, pa1);
                }
            }
        }
        ibuf = nb;
    }

    // final flush
    flush_seg(curPid, pa0, pa1, Ssum, lane);

    // ---- grid-wide barrier (152 blocks = 1/SM, co-resident) ----------------
    __threadfence();
    __syncthreads();
    if (tid == 0) {
        atomicAdd(&g_arrive, 1);
        while (*(volatile int*)&g_arrive < gridDim.x) { __nanosleep(64); }
    }
    __syncthreads();
    __threadfence();

    // ---- normalize phase: block owns p in [p0, p1) -------------------------
    {
        const int p0 = (int)(((long long)blockIdx.x * P) / GRID);
        const int p1 = (int)(((long long)(blockIdx.x + 1) * P) / GRID);
        for (int i = p0 * 128 + tid; i < p1 * 128; i += NTHR) {
            int p = i >> 7;
            float S = g_S[p];
            out[i] = g_acc[i] / ((S > 0.0f) ? S : 1.0f);
            g_acc[i] = 0.0f;                   // re-arm for next graph replay
        }
        if (has_pids) {
            float* outpids = out + (size_t)P * 128;
            for (int p = p0 + tid; p < p1; p += NTHR) outpids[p] = (float)p;
        }
        __syncthreads();                        // all reads of g_S done
        for (int p = p0 + tid; p < p1; p += NTHR) g_S[p] = 0.0f;
    }

    // ---- barrier self-reset for next replay --------------------------------
    __syncthreads();
    if (tid == 0) {
        int d = atomicAdd(&g_depart, 1);
        if (d == gridDim.x - 1) {
            g_arrive = 0;
            g_depart = 0;
            __threadfence();
        }
    }
}

// ---------------------------------------------------------------------------
extern "C" void kernel_launch(void* const* d_in, const int* in_sizes, int n_in,
                              void* d_out, int out_size) {
    const float* x   = (const float*)d_in[0];
    const int*   pid = (const int*)  d_in[1];
    const float* W1  = (const float*)d_in[2];
    const float* b1  = (const float*)d_in[3];
    const float* W2  = (const float*)d_in[4];
    const float* b2  = (const float*)d_in[5];
    float* out = (float*)d_out;

    const int n = in_sizes[1];       // N rows
    const int D = 128;

    int P;
    int has_pids;
    if (out_size % (D + 1) == 0) { P = out_size / (D + 1); has_pids = 1; }
    else                         { P = out_size / D;       has_pids = 0; }
    if (P > PMAX) P = PMAX;

    static bool attr_set = false;
    if (!attr_set) {
        cudaFuncSetAttribute(k_main,
                             cudaFuncAttributeMaxDynamicSharedMemorySize,
                             SMEM_BYTES);
        attr_set = true;
    }

    const int nUnits = (n + RPG - 1) / RPG;
    k_main<<<GRID, NTHR, SMEM_BYTES>>>(x, pid, W1, b1, W2, b2, out,
                                       n, nUnits, P, has_pids);
}

// round 14
// speedup vs baseline: 1.0246x; 1.0246x over previous
#include <cuda_runtime.h>
#include <cstdint>

// ---------------------------------------------------------------------------
// TemporalAttentionPooling (GB300 / sm_103a) — Round 13
//   scores = tanh(x @ W1 + b1) @ W2 + b2   (MLP 128->32->1)
//   per-segment softmax (max-free: bounded scores) -> pooled = sum e x / sum e
//
// R13 vs R12 (256.8 us FAILED: 8 warps -> L1 util 56%) and R11 (234.2 us,
// 12 warps -> L1 76%): utilization scales with warps in this regime, so
// trade rows-per-unit DOWN for warps UP:
//   - NWARP 12->16 (512 thr), RPG 16->12; smem 219 KB
//   - traffic/row +11% (W1 10.7 LDS/row) but +33% warps -> predicted net win
//   skeleton unchanged from R11/R12.
// ---------------------------------------------------------------------------

#define RPG     12
#define PMAX    16384
#define NWARP   16
#define NTHR    (NWARP * 32)
#define GRID    152
#define RSTRIDE 132                  // floats per staged row (528 B)
#define BUFF    (RPG * RSTRIDE)      // 1584 floats per buffer
#define WSTRIDE (2 * BUFF)           // 3168 floats per warp (2 buffers)

__device__ float g_acc[PMAX * 128];  // unnormalized pooled sums (self-zeroing)
__device__ float g_S[PMAX];          // exp-sum denominators    (self-zeroing)
__device__ int   g_arrive;           // grid barrier (self-resetting)
__device__ int   g_depart;

static __device__ __forceinline__ unsigned long long f2pack(float lo, float hi) {
    unsigned long long r;
    asm("mov.b64 %0, {%1, %2};" : "=l"(r) : "f"(lo), "f"(hi));
    return r;
}
static __device__ __forceinline__ void f2unpack(unsigned long long v, float& lo, float& hi) {
    asm("mov.b64 {%0, %1}, %2;" : "=f"(lo), "=f"(hi) : "l"(v));
}
static __device__ __forceinline__ unsigned long long ffma2(unsigned long long a,
                                                           unsigned long long b,
                                                           unsigned long long c) {
    unsigned long long d;
    asm("fma.rn.f32x2 %0, %1, %2, %3;" : "=l"(d) : "l"(a), "l"(b), "l"(c));
    return d;
}
static __device__ __forceinline__ void cp_async16(uint32_t dst, const void* src, int pred) {
    asm volatile(
        "{ .reg .pred p;\n"
        "  setp.ne.u32 p, %2, 0;\n"
        "  @p cp.async.cg.shared.global [%0], [%1], 16; }\n"
        :: "r"(dst), "l"(src), "r"(pred));
}
#define CP_COMMIT() asm volatile("cp.async.commit_group;" ::: "memory")
#define CP_WAIT1()  asm volatile("cp.async.wait_group 1;" ::: "memory")

// cheap accurate tanh: (e^{2h}-1)/(e^{2h}+1); |h| bounded so no overflow
static __device__ __forceinline__ float tanh_fast(float h) {
    float t = __expf(2.0f * h);
    return __fdividef(t - 1.0f, t + 1.0f);
}

static __device__ __forceinline__ void flush_seg(int pidv,
                                                 unsigned long long& pa0,
                                                 unsigned long long& pa1,
                                                 float& Ssum, int lane) {
    if (pidv >= 0) {
        float a, b, c, d;
        f2unpack(pa0, a, b);
        f2unpack(pa1, c, d);
        float* dst = g_acc + (size_t)pidv * 128 + 4 * lane;
        atomicAdd(dst + 0, a);
        atomicAdd(dst + 1, b);
        atomicAdd(dst + 2, c);
        atomicAdd(dst + 3, d);
        if (lane == 0) atomicAdd(&g_S[pidv], Ssum);
    }
    pa0 = 0ull; pa1 = 0ull; Ssum = 0.0f;
}

// dynamic smem: [0,16K) w1t; [16K, 16K + NWARP*WSTRIDE*4) per-warp stages
#define SMEM_BYTES (16384 + NWARP * WSTRIDE * 4)

__global__ void __launch_bounds__(NTHR, 1)
k_main(const float* __restrict__ x,
       const int*   __restrict__ pid,
       const float* __restrict__ W1,   // (128, 32) row-major
       const float* __restrict__ b1,   // (32,)
       const float* __restrict__ W2,   // (32,)
       const float* __restrict__ b2,   // (1,)
       float* __restrict__ out,        // (P,128) then pids (P,) if present
       int n, int nUnits, int P, int has_pids) {
    extern __shared__ __align__(16) char smem_raw[];
    ulonglong2* w1t   = reinterpret_cast<ulonglong2*>(smem_raw);
    float*      stage = reinterpret_cast<float*>(smem_raw + 16384);

    const int tid  = threadIdx.x;
    const int wid  = tid >> 5;
    const int lane = tid & 31;
    const int j2   = lane & 7;      // hidden group: j = 4*j2..4*j2+3
    const int r2   = lane >> 3;     // row subgroup base: rows r2+4*rr

    // ---- k-paired W1 table (packing verified R4..R12) ----------------------
    {
        float* w1f = reinterpret_cast<float*>(w1t);
        for (int q4 = tid; q4 < 4096; q4 += NTHR) {
            int q    = q4 >> 2, slot = q4 & 3;
            int kp   = q >> 4, rem = q & 15;
            int part = rem >> 3, jq = rem & 7;
            int j    = 4 * jq + 2 * part + (slot >> 1);
            int krow = 2 * kp + (slot & 1);
            w1f[q4] = W1[krow * 32 + j];
        }
    }
    const float4 b1q = reinterpret_cast<const float4*>(b1)[j2];
    const float4 w2q = reinterpret_cast<const float4*>(W2)[j2];
    const float  b2s = b2[0];
    __syncthreads();

    const uint32_t st_sh =
        (uint32_t)__cvta_generic_to_shared(stage) + (uint32_t)(wid * WSTRIDE * 4);
    float* const stw = stage + wid * WSTRIDE;

    // ---- contiguous unit range for this warp -------------------------------
    const int nW = GRID * NWARP;
    const int gw = blockIdx.x * NWARP + wid;
    const long long u0 = ((long long)gw * nUnits) / nW;
    const long long u1 = ((long long)(gw + 1) * nUnits) / nW;

    unsigned long long pa0 = 0ull, pa1 = 0ull;  // running pooled dims 4l..4l+3
    float Ssum   = 0.0f;
    int   curPid = -1;

    int ibuf = 0;
    int pidNext = -2;
    if (u0 < u1) {                    // prologue: issue unit u0 into buf 0
        const int   br  = (int)(u0 * RPG);
        const float* sp = x + (size_t)br * 128 + lane * 4;
        if (br + RPG <= n) {
#pragma unroll
            for (int r = 0; r < RPG; r++)
                cp_async16(st_sh + (uint32_t)(r * 528 + (lane << 4)),
                           sp + (size_t)r * 128, 1);
        } else {
#pragma unroll
            for (int r = 0; r < RPG; r++)
                cp_async16(st_sh + (uint32_t)(r * 528 + (lane << 4)),
                           sp + (size_t)r * 128, (br + r) < n);
        }
        if (lane < RPG && (br + lane) < n) pidNext = pid[br + lane];
    }
    CP_COMMIT();

    for (long long uu = u0; uu < u1; ++uu) {
        const int pidCur = pidNext;
        const int nb = ibuf ^ 1;
        if (uu + 1 < u1) {            // issue next unit (linear addresses)
            const int   br  = (int)((uu + 1) * RPG);
            const float* sp = x + (size_t)br * 128 + lane * 4;
            const uint32_t xbA = st_sh + (uint32_t)(nb * BUFF * 4);
            if (br + RPG <= n) {
#pragma unroll
                for (int r = 0; r < RPG; r++)
                    cp_async16(xbA + (uint32_t)(r * 528 + (lane << 4)),
                               sp + (size_t)r * 128, 1);
            } else {
#pragma unroll
                for (int r = 0; r < RPG; r++)
                    cp_async16(xbA + (uint32_t)(r * 528 + (lane << 4)),
                               sp + (size_t)r * 128, (br + r) < n);
            }
            pidNext = -2;
            if (lane < RPG && (br + lane) < n) pidNext = pid[br + lane];
        }
        CP_COMMIT();
        CP_WAIT1();                   // current unit complete

        const int baseRow   = (int)(uu * RPG);
        const int rowsValid = min(RPG, n - baseRow);
        const float* xb = stw + ibuf * BUFF;

        // ---- MLP: 12 rows, acc[3 row-subgroups][4 hidden] ------------------
        unsigned long long acc[3][4];
#pragma unroll
        for (int rr = 0; rr < 3; rr++)
#pragma unroll
            for (int jj = 0; jj < 4; jj++) acc[rr][jj] = 0ull;

#pragma unroll 8
        for (int t = 0; t < 32; t++) {
            ulonglong2 wA0 = w1t[32 * t + j2];
            ulonglong2 wA1 = w1t[32 * t + 8 + j2];
            ulonglong2 wB0 = w1t[32 * t + 16 + j2];
            ulonglong2 wB1 = w1t[32 * t + 24 + j2];
#pragma unroll
            for (int rr = 0; rr < 3; rr++) {
                const int row = r2 + 4 * rr;
                ulonglong2 xq = *reinterpret_cast<const ulonglong2*>(
                                    xb + row * RSTRIDE + t * 4);
                acc[rr][0] = ffma2(xq.x, wA0.x, acc[rr][0]);
                acc[rr][1] = ffma2(xq.x, wA0.y, acc[rr][1]);
                acc[rr][2] = ffma2(xq.x, wA1.x, acc[rr][2]);
                acc[rr][3] = ffma2(xq.x, wA1.y, acc[rr][3]);
                acc[rr][0] = ffma2(xq.y, wB0.x, acc[rr][0]);
                acc[rr][1] = ffma2(xq.y, wB0.y, acc[rr][1]);
                acc[rr][2] = ffma2(xq.y, wB1.x, acc[rr][2]);
                acc[rr][3] = ffma2(xq.y, wB1.y, acc[rr][3]);
            }
        }

        // ---- epilogue: tanh + W2 dot + j2-octet reduce -> e per row --------
        float ev[3];
#pragma unroll
        for (int rr = 0; rr < 3; rr++) {
            float s = 0.0f;
#pragma unroll
            for (int jj = 0; jj < 4; jj++) {
                float lo, hi;
                f2unpack(acc[rr][jj], lo, hi);
                float h = lo + hi + reinterpret_cast<const float*>(&b1q)[jj];
                s += tanh_fast(h) * reinterpret_cast<const float*>(&w2q)[jj];
            }
            s += __shfl_xor_sync(0xffffffffu, s, 1);
            s += __shfl_xor_sync(0xffffffffu, s, 2);
            s += __shfl_xor_sync(0xffffffffu, s, 4);
            ev[rr] = __expf(s + b2s);   // bounded scores: no overflow
        }

        // ---- pooling -------------------------------------------------------
        const int pidFirst = __shfl_sync(0xffffffffu, pidCur, 0);
        const int pidLast  = __shfl_sync(0xffffffffu, pidCur, RPG - 1);
        if (pidFirst == pidLast && rowsValid == RPG) {
            // fast path: whole unit in one segment (sorted pids)
            if (pidFirst != curPid) {
                flush_seg(curPid, pa0, pa1, Ssum, lane);
                curPid = pidFirst;
            }
            float s3 = (ev[0] + ev[1]) + ev[2];   // 3 rows per lane octet
            s3 += __shfl_xor_sync(0xffffffffu, s3, 8);
            s3 += __shfl_xor_sync(0xffffffffu, s3, 16);
            Ssum += s3;
#pragma unroll
            for (int r = 0; r < RPG; r++) {
                float ew = __shfl_sync(0xffffffffu, ev[r >> 2], (r & 3) * 8);
                ulonglong2 xq = *reinterpret_cast<const ulonglong2*>(
                                    xb + r * RSTRIDE + lane * 4);
                unsigned long long eq = f2pack(ew, ew);
                pa0 = ffma2(xq.x, eq, pa0);
                pa1 = ffma2(xq.y, eq, pa1);
            }
        } else {
            // slow path: per-row pid tracking
#pragma unroll
            for (int r = 0; r < RPG; r++) {
                if (r < rowsValid) {
                    int pr = __shfl_sync(0xffffffffu, pidCur, r);
                    if (pr != curPid) {
                        flush_seg(curPid, pa0, pa1, Ssum, lane);
                        curPid = pr;
                    }
                    float ew = __shfl_sync(0xffffffffu, ev[r >> 2], (r & 3) * 8);
                    Ssum += ew;
                    ulonglong2 xq = *reinterpret_cast<const ulonglong2*>(
                                        xb + r * RSTRIDE + lane * 4);
                    unsigned long long eq = f2pack(ew, ew);
                    pa0 = ffma2(xq.x, eq, pa0);
                    pa1 = ffma2(xq.y, eq, pa1);
                }
            }
        }
        ibuf = nb;
    }

    // final flush
    flush_seg(curPid, pa0, pa1, Ssum, lane);

    // ---- grid-wide barrier (152 blocks = 1/SM, co-resident) ----------------
    __threadfence();
    __syncthreads();
    if (tid == 0) {
        atomicAdd(&g_arrive, 1);
        while (*(volatile int*)&g_arrive < gridDim.x) { __nanosleep(64); }
    }
    __syncthreads();
    __threadfence();

    // ---- normalize phase: block owns p in [p0, p1) -------------------------
    {
        const int p0 = (int)(((long long)blockIdx.x * P) / GRID);
        const int p1 = (int)(((long long)(blockIdx.x + 1) * P) / GRID);
        for (int i = p0 * 128 + tid; i < p1 * 128; i += NTHR) {
            int p = i >> 7;
            float S = g_S[p];
            out[i] = g_acc[i] / ((S > 0.0f) ? S : 1.0f);
            g_acc[i] = 0.0f;                   // re-arm for next graph replay
        }
        if (has_pids) {
            float* outpids = out + (size_t)P * 128;
            for (int p = p0 + tid; p < p1; p += NTHR) outpids[p] = (float)p;
        }
        __syncthreads();                        // all reads of g_S done
        for (int p = p0 + tid; p < p1; p += NTHR) g_S[p] = 0.0f;
    }

    // ---- barrier self-reset for next replay --------------------------------
    __syncthreads();
    if (tid == 0) {
        int d = atomicAdd(&g_depart, 1);
        if (d == gridDim.x - 1) {
            g_arrive = 0;
            g_depart = 0;
            __threadfence();
        }
    }
}

// ---------------------------------------------------------------------------
extern "C" void kernel_launch(void* const* d_in, const int* in_sizes, int n_in,
                              void* d_out, int out_size) {
    const float* x   = (const float*)d_in[0];
    const int*   pid = (const int*)  d_in[1];
    const float* W1  = (const float*)d_in[2];
    const float* b1  = (const float*)d_in[3];
    const float* W2  = (const float*)d_in[4];
    const float* b2  = (const float*)d_in[5];
    float* out = (float*)d_out;

    const int n = in_sizes[1];       // N rows
    const int D = 128;

    int P;
    int has_pids;
    if (out_size % (D + 1) == 0) { P = out_size / (D + 1); has_pids = 1; }
    else                         { P = out_size / D;       has_pids = 0; }
    if (P > PMAX) P = PMAX;

    static bool attr_set = false;
    if (!attr_set) {
        cudaFuncSetAttribute(k_main,
                             cudaFuncAttributeMaxDynamicSharedMemorySize,
                             SMEM_BYTES);
        attr_set = true;
    }

    const int nUnits = (n + RPG - 1) / RPG;
    k_main<<<GRID, NTHR, SMEM_BYTES>>>(x, pid, W1, b1, W2, b2, out,
                                       n, nUnits, P, has_pids);
}

// round 15
// speedup vs baseline: 1.1260x; 1.0989x over previous
#include <cuda_runtime.h>
#include <cstdint>

// ---------------------------------------------------------------------------
// TemporalAttentionPooling (GB300 / sm_103a) — Round 14
//   scores = tanh(x @ W1 + b1) @ W2 + b2   (MLP 128->32->1)
//   per-segment softmax (max-free: bounded scores) -> pooled = sum e x / sum e
//
// R14 vs R11 (234.2 us, best): calibrated cost model showed MUFU co-saturated
// with L1 (tanh_fast = 2 MUFU x 512 h-values/unit = 768 SMSP-cyc/unit-wave,
// == L1's 768). Fix: tanh.approx.f32 (MUFU.TANH, 1 op, max err ~6e-4 on h,
// ~1-4e-4 on output) halves MUFU -> L1 becomes sole ceiling.
// Geometry byte-identical to R11: RPG16, NWARP12 (384 thr), RSTRIDE 132.
// ---------------------------------------------------------------------------

#define RPG     16
#define PMAX    16384
#define NWARP   12
#define NTHR    (NWARP * 32)
#define GRID    152
#define RSTRIDE 132                  // floats per staged row (528 B)
#define BUFF    (RPG * RSTRIDE)      // 2112 floats per buffer
#define WSTRIDE (2 * BUFF)           // 4224 floats per warp (2 buffers)

__device__ float g_acc[PMAX * 128];  // unnormalized pooled sums (self-zeroing)
__device__ float g_S[PMAX];          // exp-sum denominators    (self-zeroing)
__device__ int   g_arrive;           // grid barrier (self-resetting)
__device__ int   g_depart;

static __device__ __forceinline__ unsigned long long f2pack(float lo, float hi) {
    unsigned long long r;
    asm("mov.b64 %0, {%1, %2};" : "=l"(r) : "f"(lo), "f"(hi));
    return r;
}
static __device__ __forceinline__ void f2unpack(unsigned long long v, float& lo, float& hi) {
    asm("mov.b64 {%0, %1}, %2;" : "=f"(lo), "=f"(hi) : "l"(v));
}
static __device__ __forceinline__ unsigned long long ffma2(unsigned long long a,
                                                           unsigned long long b,
                                                           unsigned long long c) {
    unsigned long long d;
    asm("fma.rn.f32x2 %0, %1, %2, %3;" : "=l"(d) : "l"(a), "l"(b), "l"(c));
    return d;
}
static __device__ __forceinline__ void cp_async16(uint32_t dst, const void* src, int pred) {
    asm volatile(
        "{ .reg .pred p;\n"
        "  setp.ne.u32 p, %2, 0;\n"
        "  @p cp.async.cg.shared.global [%0], [%1], 16; }\n"
        :: "r"(dst), "l"(src), "r"(pred));
}
#define CP_COMMIT() asm volatile("cp.async.commit_group;" ::: "memory")
#define CP_WAIT1()  asm volatile("cp.async.wait_group 1;" ::: "memory")

// single-MUFU tanh (MUFU.TANH): max abs err ~2^-10.66 on h
static __device__ __forceinline__ float tanh_approx(float h) {
    float r;
    asm("tanh.approx.f32 %0, %1;" : "=f"(r) : "f"(h));
    return r;
}

static __device__ __forceinline__ void flush_seg(int pidv,
                                                 unsigned long long& pa0,
                                                 unsigned long long& pa1,
                                                 float& Ssum, int lane) {
    if (pidv >= 0) {
        float a, b, c, d;
        f2unpack(pa0, a, b);
        f2unpack(pa1, c, d);
        float* dst = g_acc + (size_t)pidv * 128 + 4 * lane;
        atomicAdd(dst + 0, a);
        atomicAdd(dst + 1, b);
        atomicAdd(dst + 2, c);
        atomicAdd(dst + 3, d);
        if (lane == 0) atomicAdd(&g_S[pidv], Ssum);
    }
    pa0 = 0ull; pa1 = 0ull; Ssum = 0.0f;
}

// dynamic smem: [0,16K) w1t; [16K, 16K + NWARP*WSTRIDE*4) per-warp stages
#define SMEM_BYTES (16384 + NWARP * WSTRIDE * 4)

__global__ void __launch_bounds__(NTHR, 1)
k_main(const float* __restrict__ x,
       const int*   __restrict__ pid,
       const float* __restrict__ W1,   // (128, 32) row-major
       const float* __restrict__ b1,   // (32,)
       const float* __restrict__ W2,   // (32,)
       const float* __restrict__ b2,   // (1,)
       float* __restrict__ out,        // (P,128) then pids (P,) if present
       int n, int nUnits, int P, int has_pids) {
    extern __shared__ __align__(16) char smem_raw[];
    ulonglong2* w1t   = reinterpret_cast<ulonglong2*>(smem_raw);
    float*      stage = reinterpret_cast<float*>(smem_raw + 16384);

    const int tid  = threadIdx.x;
    const int wid  = tid >> 5;
    const int lane = tid & 31;
    const int j2   = lane & 7;      // hidden group: j = 4*j2..4*j2+3
    const int r2   = lane >> 3;     // row subgroup base: rows r2+4*rr

    // ---- k-paired W1 table (packing verified R4..R13) ----------------------
    {
        float* w1f = reinterpret_cast<float*>(w1t);
        for (int q4 = tid; q4 < 4096; q4 += NTHR) {
            int q    = q4 >> 2, slot = q4 & 3;
            int kp   = q >> 4, rem = q & 15;
            int part = rem >> 3, jq = rem & 7;
            int j    = 4 * jq + 2 * part + (slot >> 1);
            int krow = 2 * kp + (slot & 1);
            w1f[q4] = W1[krow * 32 + j];
        }
    }
    const float4 b1q = reinterpret_cast<const float4*>(b1)[j2];
    const float4 w2q = reinterpret_cast<const float4*>(W2)[j2];
    const float  b2s = b2[0];
    __syncthreads();

    const uint32_t st_sh =
        (uint32_t)__cvta_generic_to_shared(stage) + (uint32_t)(wid * WSTRIDE * 4);
    float* const stw = stage + wid * WSTRIDE;

    // ---- contiguous unit range for this warp -------------------------------
    const int nW = GRID * NWARP;
    const int gw = blockIdx.x * NWARP + wid;
    const long long u0 = ((long long)gw * nUnits) / nW;
    const long long u1 = ((long long)(gw + 1) * nUnits) / nW;

    unsigned long long pa0 = 0ull, pa1 = 0ull;  // running pooled dims 4l..4l+3
    float Ssum   = 0.0f;
    int   curPid = -1;

    int ibuf = 0;
    int pidNext = -2;
    if (u0 < u1) {                    // prologue: issue unit u0 into buf 0
        const int   br  = (int)(u0 * RPG);
        const float* sp = x + (size_t)br * 128 + lane * 4;
        if (br + RPG <= n) {
#pragma unroll
            for (int r = 0; r < RPG; r++)
                cp_async16(st_sh + (uint32_t)(r * 528 + (lane << 4)),
                           sp + (size_t)r * 128, 1);
        } else {
#pragma unroll
            for (int r = 0; r < RPG; r++)
                cp_async16(st_sh + (uint32_t)(r * 528 + (lane << 4)),
                           sp + (size_t)r * 128, (br + r) < n);
        }
        if (lane < RPG && (br + lane) < n) pidNext = pid[br + lane];
    }
    CP_COMMIT();

    for (long long uu = u0; uu < u1; ++uu) {
        const int pidCur = pidNext;
        const int nb = ibuf ^ 1;
        if (uu + 1 < u1) {            // issue next unit (linear addresses)
            const int   br  = (int)((uu + 1) * RPG);
            const float* sp = x + (size_t)br * 128 + lane * 4;
            const uint32_t xbA = st_sh + (uint32_t)(nb * BUFF * 4);
            if (br + RPG <= n) {
#pragma unroll
                for (int r = 0; r < RPG; r++)
                    cp_async16(xbA + (uint32_t)(r * 528 + (lane << 4)),
                               sp + (size_t)r * 128, 1);
            } else {
#pragma unroll
                for (int r = 0; r < RPG; r++)
                    cp_async16(xbA + (uint32_t)(r * 528 + (lane << 4)),
                               sp + (size_t)r * 128, (br + r) < n);
            }
            pidNext = -2;
            if (lane < RPG && (br + lane) < n) pidNext = pid[br + lane];
        }
        CP_COMMIT();
        CP_WAIT1();                   // current unit complete

        const int baseRow   = (int)(uu * RPG);
        const int rowsValid = min(RPG, n - baseRow);
        const float* xb = stw + ibuf * BUFF;

        // ---- MLP: 16 rows, acc[4 row-subgroups][4 hidden] ------------------
        unsigned long long acc[4][4];
#pragma unroll
        for (int rr = 0; rr < 4; rr++)
#pragma unroll
            for (int jj = 0; jj < 4; jj++) acc[rr][jj] = 0ull;

#pragma unroll 8
        for (int t = 0; t < 32; t++) {
            ulonglong2 wA0 = w1t[32 * t + j2];
            ulonglong2 wA1 = w1t[32 * t + 8 + j2];
            ulonglong2 wB0 = w1t[32 * t + 16 + j2];
            ulonglong2 wB1 = w1t[32 * t + 24 + j2];
#pragma unroll
            for (int rr = 0; rr < 4; rr++) {
                const int row = r2 + 4 * rr;
                ulonglong2 xq = *reinterpret_cast<const ulonglong2*>(
                                    xb + row * RSTRIDE + t * 4);
                acc[rr][0] = ffma2(xq.x, wA0.x, acc[rr][0]);
                acc[rr][1] = ffma2(xq.x, wA0.y, acc[rr][1]);
                acc[rr][2] = ffma2(xq.x, wA1.x, acc[rr][2]);
                acc[rr][3] = ffma2(xq.x, wA1.y, acc[rr][3]);
                acc[rr][0] = ffma2(xq.y, wB0.x, acc[rr][0]);
                acc[rr][1] = ffma2(xq.y, wB0.y, acc[rr][1]);
                acc[rr][2] = ffma2(xq.y, wB1.x, acc[rr][2]);
                acc[rr][3] = ffma2(xq.y, wB1.y, acc[rr][3]);
            }
        }

        // ---- epilogue: tanh.approx + W2 dot + j2-octet reduce -> e per row -
        float ev[4];
#pragma unroll
        for (int rr = 0; rr < 4; rr++) {
            float s = 0.0f;
#pragma unroll
            for (int jj = 0; jj < 4; jj++) {
                float lo, hi;
                f2unpack(acc[rr][jj], lo, hi);
                float h = lo + hi + reinterpret_cast<const float*>(&b1q)[jj];
                s += tanh_approx(h) * reinterpret_cast<const float*>(&w2q)[jj];
            }
            s += __shfl_xor_sync(0xffffffffu, s, 1);
            s += __shfl_xor_sync(0xffffffffu, s, 2);
            s += __shfl_xor_sync(0xffffffffu, s, 4);
            ev[rr] = __expf(s + b2s);   // bounded scores: no overflow
        }

        // ---- pooling -------------------------------------------------------
        const int pidFirst = __shfl_sync(0xffffffffu, pidCur, 0);
        const int pidLast  = __shfl_sync(0xffffffffu, pidCur, RPG - 1);
        if (pidFirst == pidLast && rowsValid == RPG) {
            // fast path: whole unit in one segment (sorted pids)
            if (pidFirst != curPid) {
                flush_seg(curPid, pa0, pa1, Ssum, lane);
                curPid = pidFirst;
            }
            float s4 = (ev[0] + ev[1]) + (ev[2] + ev[3]);
            s4 += __shfl_xor_sync(0xffffffffu, s4, 8);
            s4 += __shfl_xor_sync(0xffffffffu, s4, 16);
            Ssum += s4;
#pragma unroll
            for (int r = 0; r < RPG; r++) {
                float ew = __shfl_sync(0xffffffffu, ev[r >> 2], (r & 3) * 8);
                ulonglong2 xq = *reinterpret_cast<const ulonglong2*>(
                                    xb + r * RSTRIDE + lane * 4);
                unsigned long long eq = f2pack(ew, ew);
                pa0 = ffma2(xq.x, eq, pa0);
                pa1 = ffma2(xq.y, eq, pa1);
            }
        } else {
            // slow path: per-row pid tracking
#pragma unroll
            for (int r = 0; r < RPG; r++) {
                if (r < rowsValid) {
                    int pr = __shfl_sync(0xffffffffu, pidCur, r);
                    if (pr != curPid) {
                        flush_seg(curPid, pa0, pa1, Ssum, lane);
                        curPid = pr;
                    }
                    float ew = __shfl_sync(0xffffffffu, ev[r >> 2], (r & 3) * 8);
                    Ssum += ew;
                    ulonglong2 xq = *reinterpret_cast<const ulonglong2*>(
                                        xb + r * RSTRIDE + lane * 4);
                    unsigned long long eq = f2pack(ew, ew);
                    pa0 = ffma2(xq.x, eq, pa0);
                    pa1 = ffma2(xq.y, eq, pa1);
                }
            }
        }
        ibuf = nb;
    }

    // final flush
    flush_seg(curPid, pa0, pa1, Ssum, lane);

    // ---- grid-wide barrier (152 blocks = 1/SM, co-resident) ----------------
    __threadfence();
    __syncthreads();
    if (tid == 0) {
        atomicAdd(&g_arrive, 1);
        while (*(volatile int*)&g_arrive < gridDim.x) { __nanosleep(64); }
    }
    __syncthreads();
    __threadfence();

    // ---- normalize phase: block owns p in [p0, p1) -------------------------
    {
        const int p0 = (int)(((long long)blockIdx.x * P) / GRID);
        const int p1 = (int)(((long long)(blockIdx.x + 1) * P) / GRID);
        for (int i = p0 * 128 + tid; i < p1 * 128; i += NTHR) {
            int p = i >> 7;
            float S = g_S[p];
            out[i] = g_acc[i] / ((S > 0.0f) ? S : 1.0f);
            g_acc[i] = 0.0f;                   // re-arm for next graph replay
        }
        if (has_pids) {
            float* outpids = out + (size_t)P * 128;
            for (int p = p0 + tid; p < p1; p += NTHR) outpids[p] = (float)p;
        }
        __syncthreads();                        // all reads of g_S done
        for (int p = p0 + tid; p < p1; p += NTHR) g_S[p] = 0.0f;
    }

    // ---- barrier self-reset for next replay --------------------------------
    __syncthreads();
    if (tid == 0) {
        int d = atomicAdd(&g_depart, 1);
        if (d == gridDim.x - 1) {
            g_arrive = 0;
            g_depart = 0;
            __threadfence();
        }
    }
}

// ---------------------------------------------------------------------------
extern "C" void kernel_launch(void* const* d_in, const int* in_sizes, int n_in,
                              void* d_out, int out_size) {
    const float* x   = (const float*)d_in[0];
    const int*   pid = (const int*)  d_in[1];
    const float* W1  = (const float*)d_in[2];
    const float* b1  = (const float*)d_in[3];
    const float* W2  = (const float*)d_in[4];
    const float* b2  = (const float*)d_in[5];
    float* out = (float*)d_out;

    const int n = in_sizes[1];       // N rows
    const int D = 128;

    int P;
    int has_pids;
    if (out_size % (D + 1) == 0) { P = out_size / (D + 1); has_pids = 1; }
    else                         { P = out_size / D;       has_pids = 0; }
    if (P > PMAX) P = PMAX;

    static bool attr_set = false;
    if (!attr_set) {
        cudaFuncSetAttribute(k_main,
                             cudaFuncAttributeMaxDynamicSharedMemorySize,
                             SMEM_BYTES);
        attr_set = true;
    }

    const int nUnits = (n + RPG - 1) / RPG;
    k_main<<<GRID, NTHR, SMEM_BYTES>>>(x, pid, W1, b1, W2, b2, out,
                                       n, nUnits, P, has_pids);
}

// round 16
// speedup vs baseline: 2.2289x; 1.9794x over previous
#include <cuda_runtime.h>
#include <cstdint>

// ---------------------------------------------------------------------------
// TemporalAttentionPooling (GB300 / sm_103a) — Round 15
//   scores = tanh(x @ W1 + b1) @ W2 + b2   (MLP 128->32->1)
//   per-segment softmax (max-free: bounded scores) -> pooled = sum e x / sum e
//
// R15 vs R14 (228.0 us; 72% of issued instrs are FFMA2 -> issue/fma bound):
//   Score GEMM moves to tensor cores: tf32 mma.sync.m16n8k8 (64 mma/unit
//   replaces 1024 FFMA2). A from staged x (LDS.32, conflict-free via
//   RSTRIDE=132), B from a lane-ordered tf32 W1 table (LDS.64 contiguous).
//   rna-rounded tf32 both operands, fp32 accumulate: est. out rel_err ~2e-4.
//   Staging / pooling / atomic flush / fused normalize unchanged (R11 skeleton,
//   RPG16, NWARP12).
// ---------------------------------------------------------------------------

#define RPG     16
#define PMAX    16384
#define NWARP   12
#define NTHR    (NWARP * 32)
#define GRID    152
#define RSTRIDE 132                  // floats per staged row (528 B)
#define BUFF    (RPG * RSTRIDE)      // 2112 floats per buffer
#define WSTRIDE (2 * BUFF)           // 4224 floats per warp (2 buffers)

__device__ float g_acc[PMAX * 128];  // unnormalized pooled sums (self-zeroing)
__device__ float g_S[PMAX];          // exp-sum denominators    (self-zeroing)
__device__ int   g_arrive;           // grid barrier (self-resetting)
__device__ int   g_depart;

static __device__ __forceinline__ unsigned long long f2pack(float lo, float hi) {
    unsigned long long r;
    asm("mov.b64 %0, {%1, %2};" : "=l"(r) : "f"(lo), "f"(hi));
    return r;
}
static __device__ __forceinline__ void f2unpack(unsigned long long v, float& lo, float& hi) {
    asm("mov.b64 {%0, %1}, %2;" : "=f"(lo), "=f"(hi) : "l"(v));
}
static __device__ __forceinline__ unsigned long long ffma2(unsigned long long a,
                                                           unsigned long long b,
                                                           unsigned long long c) {
    unsigned long long d;
    asm("fma.rn.f32x2 %0, %1, %2, %3;" : "=l"(d) : "l"(a), "l"(b), "l"(c));
    return d;
}
static __device__ __forceinline__ void cp_async16(uint32_t dst, const void* src, int pred) {
    asm volatile(
        "{ .reg .pred p;\n"
        "  setp.ne.u32 p, %2, 0;\n"
        "  @p cp.async.cg.shared.global [%0], [%1], 16; }\n"
        :: "r"(dst), "l"(src), "r"(pred));
}
#define CP_COMMIT() asm volatile("cp.async.commit_group;" ::: "memory")
#define CP_WAIT1()  asm volatile("cp.async.wait_group 1;" ::: "memory")

// single-MUFU tanh (MUFU.TANH)
static __device__ __forceinline__ float tanh_approx(float h) {
    float r;
    asm("tanh.approx.f32 %0, %1;" : "=f"(r) : "f"(h));
    return r;
}
// round-to-nearest tf32 (b32 pattern with low mantissa bits cleared)
static __device__ __forceinline__ uint32_t f2tf32(float f) {
    uint32_t r;
    asm("cvt.rna.tf32.f32 %0, %1;" : "=r"(r) : "f"(f));
    return r;
}
// D += A(m16k8,row) * B(k8n8,col), tf32 in, f32 accumulate
static __device__ __forceinline__ void mma_tf32(float& d0, float& d1, float& d2, float& d3,
                                                uint32_t a0, uint32_t a1, uint32_t a2, uint32_t a3,
                                                uint32_t b0, uint32_t b1) {
    asm volatile(
        "mma.sync.aligned.m16n8k8.row.col.f32.tf32.tf32.f32 "
        "{%0,%1,%2,%3}, {%4,%5,%6,%7}, {%8,%9}, {%0,%1,%2,%3};"
        : "+f"(d0), "+f"(d1), "+f"(d2), "+f"(d3)
        : "r"(a0), "r"(a1), "r"(a2), "r"(a3), "r"(b0), "r"(b1));
}

static __device__ __forceinline__ void flush_seg(int pidv,
                                                 unsigned long long& pa0,
                                                 unsigned long long& pa1,
                                                 float& Ssum, int lane) {
    if (pidv >= 0) {
        float a, b, c, d;
        f2unpack(pa0, a, b);
        f2unpack(pa1, c, d);
        float* dst = g_acc + (size_t)pidv * 128 + 4 * lane;
        atomicAdd(dst + 0, a);
        atomicAdd(dst + 1, b);
        atomicAdd(dst + 2, c);
        atomicAdd(dst + 3, d);
        if (lane == 0) atomicAdd(&g_S[pidv], Ssum);
    }
    pa0 = 0ull; pa1 = 0ull; Ssum = 0.0f;
}

// dynamic smem: [0,16K) w1frag (float2[2048], lane-ordered tf32 B frags);
//               [16K, 16K + NWARP*WSTRIDE*4) per-warp stages
#define SMEM_BYTES (16384 + NWARP * WSTRIDE * 4)

__global__ void __launch_bounds__(NTHR, 1)
k_main(const float* __restrict__ x,
       const int*   __restrict__ pid,
       const float* __restrict__ W1,   // (128, 32) row-major
       const float* __restrict__ b1,   // (32,)
       const float* __restrict__ W2,   // (32,)
       const float* __restrict__ b2,   // (1,)
       float* __restrict__ out,        // (P,128) then pids (P,) if present
       int n, int nUnits, int P, int has_pids) {
    extern __shared__ __align__(16) char smem_raw[];
    float2* w1f   = reinterpret_cast<float2*>(smem_raw);
    float*  stage = reinterpret_cast<float*>(smem_raw + 16384);

    const int tid  = threadIdx.x;
    const int wid  = tid >> 5;
    const int lane = tid & 31;
    const int g    = lane >> 2;     // mma groupID (row / n-col role)
    const int tig  = lane & 3;      // threadID in group (k / 2n role)

    // ---- tf32 B-fragment table: w1f[(ks*4+nt)*32 + lane] =
    //      { W1[8ks+tig][8nt+g], W1[8ks+tig+4][8nt+g] }, rna-rounded ---------
    for (int f = tid; f < 2048; f += NTHR) {
        int l  = f & 31, nt = (f >> 5) & 3, ks = f >> 7;
        int tg = l & 3,  gg = l >> 2;
        int j  = 8 * nt + gg;
        float lo = W1[(8 * ks + tg)     * 32 + j];
        float hi = W1[(8 * ks + tg + 4) * 32 + j];
        w1f[f] = make_float2(__uint_as_float(f2tf32(lo)),
                             __uint_as_float(f2tf32(hi)));
    }
    // per-lane bias / W2 for D columns j = 8nt+2tig, 8nt+2tig+1
    float b1a[4], b1b[4], w2a[4], w2b[4];
#pragma unroll
    for (int nt = 0; nt < 4; nt++) {
        b1a[nt] = b1[8 * nt + 2 * tig];
        b1b[nt] = b1[8 * nt + 2 * tig + 1];
        w2a[nt] = W2[8 * nt + 2 * tig];
        w2b[nt] = W2[8 * nt + 2 * tig + 1];
    }
    const float b2s = b2[0];
    __syncthreads();

    const uint32_t st_sh =
        (uint32_t)__cvta_generic_to_shared(stage) + (uint32_t)(wid * WSTRIDE * 4);
    float* const stw = stage + wid * WSTRIDE;

    // ---- contiguous unit range for this warp -------------------------------
    const int nW = GRID * NWARP;
    const int gw = blockIdx.x * NWARP + wid;
    const long long u0 = ((long long)gw * nUnits) / nW;
    const long long u1 = ((long long)(gw + 1) * nUnits) / nW;

    unsigned long long pa0 = 0ull, pa1 = 0ull;  // running pooled dims 4l..4l+3
    float Ssum   = 0.0f;
    int   curPid = -1;

    int ibuf = 0;
    int pidNext = -2;
    if (u0 < u1) {                    // prologue: issue unit u0 into buf 0
        const int   br  = (int)(u0 * RPG);
        const float* sp = x + (size_t)br * 128 + lane * 4;
        if (br + RPG <= n) {
#pragma unroll
            for (int r = 0; r < RPG; r++)
                cp_async16(st_sh + (uint32_t)(r * 528 + (lane << 4)),
                           sp + (size_t)r * 128, 1);
        } else {
#pragma unroll
            for (int r = 0; r < RPG; r++)
                cp_async16(st_sh + (uint32_t)(r * 528 + (lane << 4)),
                           sp + (size_t)r * 128, (br + r) < n);
        }
        if (lane < RPG && (br + lane) < n) pidNext = pid[br + lane];
    }
    CP_COMMIT();

    for (long long uu = u0; uu < u1; ++uu) {
        const int pidCur = pidNext;
        const int nb = ibuf ^ 1;
        if (uu + 1 < u1) {            // issue next unit (linear addresses)
            const int   br  = (int)((uu + 1) * RPG);
            const float* sp = x + (size_t)br * 128 + lane * 4;
            const uint32_t xbA = st_sh + (uint32_t)(nb * BUFF * 4);
            if (br + RPG <= n) {
#pragma unroll
                for (int r = 0; r < RPG; r++)
                    cp_async16(xbA + (uint32_t)(r * 528 + (lane << 4)),
                               sp + (size_t)r * 128, 1);
            } else {
#pragma unroll
                for (int r = 0; r < RPG; r++)
                    cp_async16(xbA + (uint32_t)(r * 528 + (lane << 4)),
                               sp + (size_t)r * 128, (br + r) < n);
            }
            pidNext = -2;
            if (lane < RPG && (br + lane) < n) pidNext = pid[br + lane];
        }
        CP_COMMIT();
        CP_WAIT1();                   // current unit complete

        const int baseRow   = (int)(uu * RPG);
        const int rowsValid = min(RPG, n - baseRow);
        const float* xb = stw + ibuf * BUFF;

        // ---- H = X(16x128) * W1(128x32) via 64x tf32 mma -------------------
        float d[4][4];
#pragma unroll
        for (int nt = 0; nt < 4; nt++)
#pragma unroll
            for (int q = 0; q < 4; q++) d[nt][q] = 0.0f;

        const float* xg0 = xb + g * RSTRIDE + tig;         // row g
        const float* xg8 = xb + (g + 8) * RSTRIDE + tig;   // row g+8
#pragma unroll
        for (int ks = 0; ks < 16; ks++) {
            // A frag (row-major m16k8): a0=[g][tig] a1=[g+8][tig]
            //                           a2=[g][tig+4] a3=[g+8][tig+4]
            uint32_t a0 = f2tf32(xg0[8 * ks]);
            uint32_t a1 = f2tf32(xg8[8 * ks]);
            uint32_t a2 = f2tf32(xg0[8 * ks + 4]);
            uint32_t a3 = f2tf32(xg8[8 * ks + 4]);
#pragma unroll
            for (int nt = 0; nt < 4; nt++) {
                float2 bb = w1f[(ks * 4 + nt) * 32 + lane];
                mma_tf32(d[nt][0], d[nt][1], d[nt][2], d[nt][3],
                         a0, a1, a2, a3,
                         __float_as_uint(bb.x), __float_as_uint(bb.y));
            }
        }

        // ---- epilogue: tanh + W2 dot; D cols 2tig/2tig+1, rows g and g+8 ---
        float pA = 0.0f, pB = 0.0f;
#pragma unroll
        for (int nt = 0; nt < 4; nt++) {
            pA += tanh_approx(d[nt][0] + b1a[nt]) * w2a[nt];
            pA += tanh_approx(d[nt][1] + b1b[nt]) * w2b[nt];
            pB += tanh_approx(d[nt][2] + b1a[nt]) * w2a[nt];
            pB += tanh_approx(d[nt][3] + b1b[nt]) * w2b[nt];
        }
        // reduce over tig (lanes 4g..4g+3)
        pA += __shfl_xor_sync(0xffffffffu, pA, 1);
        pA += __shfl_xor_sync(0xffffffffu, pA, 2);
        pB += __shfl_xor_sync(0xffffffffu, pB, 1);
        pB += __shfl_xor_sync(0xffffffffu, pB, 2);
        const float evA = __expf(pA + b2s);   // e for row g    (bounded)
        const float evB = __expf(pB + b2s);   // e for row g+8

        // ---- pooling -------------------------------------------------------
        const int pidFirst = __shfl_sync(0xffffffffu, pidCur, 0);
        const int pidLast  = __shfl_sync(0xffffffffu, pidCur, RPG - 1);
        if (pidFirst == pidLast && rowsValid == RPG) {
            // fast path: whole unit one segment
            if (pidFirst != curPid) {
                flush_seg(curPid, pa0, pa1, Ssum, lane);
                curPid = pidFirst;
            }
            float v = evA + evB;                  // sum over g via xor 4/8/16
            v += __shfl_xor_sync(0xffffffffu, v, 4);
            v += __shfl_xor_sync(0xffffffffu, v, 8);
            v += __shfl_xor_sync(0xffffffffu, v, 16);
            Ssum += v;
#pragma unroll
            for (int r = 0; r < RPG; r++) {
                float ew = __shfl_sync(0xffffffffu, (r < 8) ? evA : evB,
                                       (r & 7) << 2);
                ulonglong2 xq = *reinterpret_cast<const ulonglong2*>(
                                    xb + r * RSTRIDE + lane * 4);
                unsigned long long eq = f2pack(ew, ew);
                pa0 = ffma2(xq.x, eq, pa0);
                pa1 = ffma2(xq.y, eq, pa1);
            }
        } else {
            // slow path: per-row pid tracking
#pragma unroll
            for (int r = 0; r < RPG; r++) {
                if (r < rowsValid) {
                    int pr = __shfl_sync(0xffffffffu, pidCur, r);
                    if (pr != curPid) {
                        flush_seg(curPid, pa0, pa1, Ssum, lane);
                        curPid = pr;
                    }
                    float ew = __shfl_sync(0xffffffffu, (r < 8) ? evA : evB,
                                           (r & 7) << 2);
                    Ssum += ew;
                    ulonglong2 xq = *reinterpret_cast<const ulonglong2*>(
                                        xb + r * RSTRIDE + lane * 4);
                    unsigned long long eq = f2pack(ew, ew);
                    pa0 = ffma2(xq.x, eq, pa0);
                    pa1 = ffma2(xq.y, eq, pa1);
                }
            }
        }
        ibuf = nb;
    }

    // final flush
    flush_seg(curPid, pa0, pa1, Ssum, lane);

    // ---- grid-wide barrier (152 blocks = 1/SM, co-resident) ----------------
    __threadfence();
    __syncthreads();
    if (tid == 0) {
        atomicAdd(&g_arrive, 1);
        while (*(volatile int*)&g_arrive < gridDim.x) { __nanosleep(64); }
    }
    __syncthreads();
    __threadfence();

    // ---- normalize phase: block owns p in [p0, p1) -------------------------
    {
        const int p0 = (int)(((long long)blockIdx.x * P) / GRID);
        const int p1 = (int)(((long long)(blockIdx.x + 1) * P) / GRID);
        for (int i = p0 * 128 + tid; i < p1 * 128; i += NTHR) {
            int p = i >> 7;
            float S = g_S[p];
            out[i] = g_acc[i] / ((S > 0.0f) ? S : 1.0f);
            g_acc[i] = 0.0f;                   // re-arm for next graph replay
        }
        if (has_pids) {
            float* outpids = out + (size_t)P * 128;
            for (int p = p0 + tid; p < p1; p += NTHR) outpids[p] = (float)p;
        }
        __syncthreads();                        // all reads of g_S done
        for (int p = p0 + tid; p < p1; p += NTHR) g_S[p] = 0.0f;
    }

    // ---- barrier self-reset for next replay --------------------------------
    __syncthreads();
    if (tid == 0) {
        int d = atomicAdd(&g_depart, 1);
        if (d == gridDim.x - 1) {
            g_arrive = 0;
            g_depart = 0;
            __threadfence();
        }
    }
}

// ---------------------------------------------------------------------------
extern "C" void kernel_launch(void* const* d_in, const int* in_sizes, int n_in,
                              void* d_out, int out_size) {
    const float* x   = (const float*)d_in[0];
    const int*   pid = (const int*)  d_in[1];
    const float* W1  = (const float*)d_in[2];
    const float* b1  = (const float*)d_in[3];
    const float* W2  = (const float*)d_in[4];
    const float* b2  = (const float*)d_in[5];
    float* out = (float*)d_out;

    const int n = in_sizes[1];       // N rows
    const int D = 128;

    int P;
    int has_pids;
    if (out_size % (D + 1) == 0) { P = out_size / (D + 1); has_pids = 1; }
    else                         { P = out_size / D;       has_pids = 0; }
    if (P > PMAX) P = PMAX;

    static bool attr_set = false;
    if (!attr_set) {
        cudaFuncSetAttribute(k_main,
                             cudaFuncAttributeMaxDynamicSharedMemorySize,
                             SMEM_BYTES);
        attr_set = true;
    }

    const int nUnits = (n + RPG - 1) / RPG;
    k_main<<<GRID, NTHR, SMEM_BYTES>>>(x, pid, W1, b1, W2, b2, out,
                                       n, nUnits, P, has_pids);
}